// round 1
// baseline (speedup 1.0000x reference)
#include <cuda_runtime.h>
#include <cuda_fp16.h>
#include <cstdint>
#include <cstddef>

// Flash-attention-2 forward, fp16 tensor-core path (mma.sync.m16n8k16).
// B=2, H=16, S=2048, D=64, fp32 in/out.
// - Q pre-scaled by log2(e)/sqrt(D), held in registers as fp16 A-fragments.
// - K tile in smem [key][d] fp16, fragments via ldmatrix.x4 (non-trans).
// - V tile in smem [key][d] fp16, fragments via ldmatrix.x4.trans.
// - Online softmax in fp32 with ex2.approx; P packed to fp16 directly from the
//   accumulator layout (C-layout == A-layout pairing for m16n8k16).

namespace {

constexpr int S  = 2048;
constexpr int D  = 64;
constexpr int BM = 64;   // query rows per CTA (4 warps x 16)
constexpr int BN = 64;   // keys per tile
constexpr int KST = 72;  // smem row stride in halves (144 B) -> conflict-free LDSM

__device__ __forceinline__ float ex2(float x) {
    float y;
    asm volatile("ex2.approx.ftz.f32 %0, %1;" : "=f"(y) : "f"(x));
    return y;
}

__device__ __forceinline__ uint32_t packh2(float a, float b) {
    __half2 h = __floats2half2_rn(a, b);
    return *reinterpret_cast<uint32_t*>(&h);
}

__device__ __forceinline__ void ldsm_x4(uint32_t& d0, uint32_t& d1, uint32_t& d2, uint32_t& d3,
                                        uint32_t addr) {
    asm volatile("ldmatrix.sync.aligned.m8n8.x4.shared.b16 {%0,%1,%2,%3}, [%4];"
                 : "=r"(d0), "=r"(d1), "=r"(d2), "=r"(d3) : "r"(addr));
}

__device__ __forceinline__ void ldsm_x4_t(uint32_t& d0, uint32_t& d1, uint32_t& d2, uint32_t& d3,
                                          uint32_t addr) {
    asm volatile("ldmatrix.sync.aligned.m8n8.x4.trans.shared.b16 {%0,%1,%2,%3}, [%4];"
                 : "=r"(d0), "=r"(d1), "=r"(d2), "=r"(d3) : "r"(addr));
}

__device__ __forceinline__ void mma16816(float* c,
                                         uint32_t a0, uint32_t a1, uint32_t a2, uint32_t a3,
                                         uint32_t b0, uint32_t b1) {
    asm volatile("mma.sync.aligned.m16n8k16.row.col.f32.f16.f16.f32 "
                 "{%0,%1,%2,%3}, {%4,%5,%6,%7}, {%8,%9}, {%0,%1,%2,%3};"
                 : "+f"(c[0]), "+f"(c[1]), "+f"(c[2]), "+f"(c[3])
                 : "r"(a0), "r"(a1), "r"(a2), "r"(a3), "r"(b0), "r"(b1));
}

__global__ void __launch_bounds__(128)
fa_fwd(const float* __restrict__ Qg, const float* __restrict__ Kg,
       const float* __restrict__ Vg, float* __restrict__ Og) {
    __shared__ __align__(16) __half Ksh[BN * KST];
    __shared__ __align__(16) __half Vsh[BN * KST];

    const int bh    = blockIdx.y;
    const int mbase = blockIdx.x * BM;
    const float* Qp = Qg + (size_t)bh * S * D;
    const float* Kp = Kg + (size_t)bh * S * D;
    const float* Vp = Vg + (size_t)bh * S * D;
    float*       Op = Og + (size_t)bh * S * D;

    const int tid  = threadIdx.x;
    const int warp = tid >> 5;
    const int lane = tid & 31;
    const int g    = lane >> 2;  // row-in-16 group
    const int q    = lane & 3;   // quad position
    const int r0   = mbase + warp * 16 + g;
    const int r1   = r0 + 8;

    // scale * log2(e): softmax done in base 2
    const float cs = 0.125f * 1.4426950408889634f;

    // ---- Q fragments (scaled fp16), 4 k-tiles of 16 ----
    uint32_t qa[4][4];
#pragma unroll
    for (int kt = 0; kt < 4; ++kt) {
        const int c = kt * 16 + 2 * q;
        float2 t;
        t = *(const float2*)(Qp + (size_t)r0 * D + c);
        qa[kt][0] = packh2(t.x * cs, t.y * cs);
        t = *(const float2*)(Qp + (size_t)r1 * D + c);
        qa[kt][1] = packh2(t.x * cs, t.y * cs);
        t = *(const float2*)(Qp + (size_t)r0 * D + c + 8);
        qa[kt][2] = packh2(t.x * cs, t.y * cs);
        t = *(const float2*)(Qp + (size_t)r1 * D + c + 8);
        qa[kt][3] = packh2(t.x * cs, t.y * cs);
    }

    float oacc[8][4];
#pragma unroll
    for (int j = 0; j < 8; ++j)
#pragma unroll
        for (int k = 0; k < 4; ++k) oacc[j][k] = 0.f;

    const float NEGINF = -1e30f;
    float mrow0 = NEGINF, mrow1 = NEGINF;
    float lrow0 = 0.f, lrow1 = 0.f;

    const uint32_t ks_base = (uint32_t)__cvta_generic_to_shared(Ksh);
    const uint32_t vs_base = (uint32_t)__cvta_generic_to_shared(Vsh);

    // ldmatrix per-lane address components
    const int lj = lane >> 3, lr = lane & 7;
    const int krow = (lj & 2) * 4 + lr;  // K non-trans: M2/M3 -> +8 rows (next n-tile)
    const int kcol = (lj & 1) * 8;       //              M1/M3 -> +8 cols (b1)
    const int vrow = (lj & 1) * 8 + lr;  // V trans:     M1/M3 -> +8 rows (b1)
    const int vcol = (lj & 2) * 4;       //              M2/M3 -> +8 cols (next n-tile)

    for (int nt = 0; nt < S / BN; ++nt) {
        const float* Kt = Kp + (size_t)nt * BN * D;
        const float* Vt = Vp + (size_t)nt * BN * D;

        __syncthreads();
        // Load K and V tiles, fp32 -> fp16, coalesced float4 reads
#pragma unroll
        for (int i = 0; i < (BN * D / 4) / 128; ++i) {  // 8 iterations
            const int idx = tid + i * 128;
            const int row = idx >> 4;
            const int c4  = (idx & 15) * 4;
            float4 kv = *(const float4*)(Kt + row * D + c4);
            float4 vv = *(const float4*)(Vt + row * D + c4);
            __half2* kd = reinterpret_cast<__half2*>(&Ksh[row * KST + c4]);
            kd[0] = __floats2half2_rn(kv.x, kv.y);
            kd[1] = __floats2half2_rn(kv.z, kv.w);
            __half2* vd = reinterpret_cast<__half2*>(&Vsh[row * KST + c4]);
            vd[0] = __floats2half2_rn(vv.x, vv.y);
            vd[1] = __floats2half2_rn(vv.z, vv.w);
        }
        __syncthreads();

        // ---- S = (Q*cs) K^T  (units: log2) ----
        float sacc[8][4];
#pragma unroll
        for (int j = 0; j < 8; ++j)
#pragma unroll
            for (int k = 0; k < 4; ++k) sacc[j][k] = 0.f;

#pragma unroll
        for (int np = 0; np < 4; ++np) {
#pragma unroll
            for (int kt = 0; kt < 4; ++kt) {
                uint32_t b0, b1, b2, b3;
                const uint32_t addr =
                    ks_base + 2u * (uint32_t)((np * 16 + krow) * KST + kt * 16 + kcol);
                ldsm_x4(b0, b1, b2, b3, addr);
                mma16816(sacc[2 * np],     qa[kt][0], qa[kt][1], qa[kt][2], qa[kt][3], b0, b1);
                mma16816(sacc[2 * np + 1], qa[kt][0], qa[kt][1], qa[kt][2], qa[kt][3], b2, b3);
            }
        }

        // ---- online softmax (base-2) ----
        float mx0 = NEGINF, mx1 = NEGINF;
#pragma unroll
        for (int j = 0; j < 8; ++j) {
            mx0 = fmaxf(mx0, fmaxf(sacc[j][0], sacc[j][1]));
            mx1 = fmaxf(mx1, fmaxf(sacc[j][2], sacc[j][3]));
        }
        mx0 = fmaxf(mx0, __shfl_xor_sync(0xffffffffu, mx0, 1));
        mx0 = fmaxf(mx0, __shfl_xor_sync(0xffffffffu, mx0, 2));
        mx1 = fmaxf(mx1, __shfl_xor_sync(0xffffffffu, mx1, 1));
        mx1 = fmaxf(mx1, __shfl_xor_sync(0xffffffffu, mx1, 2));

        const float mn0 = fmaxf(mrow0, mx0);
        const float mn1 = fmaxf(mrow1, mx1);
        const float al0 = ex2(mrow0 - mn0);
        const float al1 = ex2(mrow1 - mn1);
        mrow0 = mn0; mrow1 = mn1;

        float rs0 = 0.f, rs1 = 0.f;
        uint32_t pa[8], pb[8];
#pragma unroll
        for (int j = 0; j < 8; ++j) {
            const float p0 = ex2(sacc[j][0] - mn0);
            const float p1 = ex2(sacc[j][1] - mn0);
            const float p2 = ex2(sacc[j][2] - mn1);
            const float p3 = ex2(sacc[j][3] - mn1);
            rs0 += p0 + p1;
            rs1 += p2 + p3;
            pa[j] = packh2(p0, p1);
            pb[j] = packh2(p2, p3);
        }
        rs0 += __shfl_xor_sync(0xffffffffu, rs0, 1);
        rs0 += __shfl_xor_sync(0xffffffffu, rs0, 2);
        rs1 += __shfl_xor_sync(0xffffffffu, rs1, 1);
        rs1 += __shfl_xor_sync(0xffffffffu, rs1, 2);
        lrow0 = lrow0 * al0 + rs0;
        lrow1 = lrow1 * al1 + rs1;

#pragma unroll
        for (int j = 0; j < 8; ++j) {
            oacc[j][0] *= al0; oacc[j][1] *= al0;
            oacc[j][2] *= al1; oacc[j][3] *= al1;
        }

        // ---- O += P V  (A frags come straight from packed accumulator) ----
#pragma unroll
        for (int kt = 0; kt < 4; ++kt) {
            const uint32_t a0 = pa[2 * kt], a1 = pb[2 * kt];
            const uint32_t a2 = pa[2 * kt + 1], a3 = pb[2 * kt + 1];
#pragma unroll
            for (int np = 0; np < 4; ++np) {
                uint32_t b0, b1, b2, b3;
                const uint32_t addr =
                    vs_base + 2u * (uint32_t)((kt * 16 + vrow) * KST + np * 16 + vcol);
                ldsm_x4_t(b0, b1, b2, b3, addr);
                mma16816(oacc[2 * np],     a0, a1, a2, a3, b0, b1);
                mma16816(oacc[2 * np + 1], a0, a1, a2, a3, b2, b3);
            }
        }
    }

    // ---- epilogue ----
    const float inv0 = 1.f / lrow0;
    const float inv1 = 1.f / lrow1;
#pragma unroll
    for (int j = 0; j < 8; ++j) {
        float2 o0 = make_float2(oacc[j][0] * inv0, oacc[j][1] * inv0);
        float2 o1 = make_float2(oacc[j][2] * inv1, oacc[j][3] * inv1);
        *(float2*)(Op + (size_t)r0 * D + j * 8 + 2 * q) = o0;
        *(float2*)(Op + (size_t)r1 * D + j * 8 + 2 * q) = o1;
    }
}

}  // namespace

extern "C" void kernel_launch(void* const* d_in, const int* /*in_sizes*/, int /*n_in*/,
                              void* d_out, int /*out_size*/) {
    const float* Q = (const float*)d_in[0];
    const float* K = (const float*)d_in[1];
    const float* V = (const float*)d_in[2];
    float* O = (float*)d_out;

    dim3 grid(S / BM, 2 * 16);  // (q-tiles, B*H)
    fa_fwd<<<grid, 128>>>(Q, K, V, O);
}

// round 10
// speedup vs baseline: 1.2043x; 1.2043x over previous
#include <cuda_runtime.h>
#include <cuda_fp16.h>
#include <cstdint>
#include <cstddef>

// Flash-attention-2 forward, fp16 tensor-core path (mma.sync.m16n8k16).
// R2 design (resubmit #8 after infra timeouts): K/V pre-converted to fp16 in
// __device__ scratch by a pre-pass kernel; mainloop uses cp.async.cg 16B
// copies into double-buffered smem, one __syncthreads per tile, load(nt+1)
// overlapped with compute(nt).

namespace {

constexpr int S  = 2048;
constexpr int D  = 64;
constexpr int BM = 64;   // query rows per CTA (4 warps x 16)
constexpr int BN = 64;   // keys per tile
constexpr int NT = S / BN;
constexpr int KST = 72;  // smem row stride in halves (144 B) -> conflict-free LDSM
constexpr int BH = 2 * 16;
constexpr size_t ELEMS = (size_t)BH * S * D;  // 4,194,304 per tensor

__device__ __half g_Kh[ELEMS];
__device__ __half g_Vh[ELEMS];

__global__ void __launch_bounds__(256)
cvt_kv(const float* __restrict__ K, const float* __restrict__ V) {
    const int i = blockIdx.x * blockDim.x + threadIdx.x;  // float4 index
    const int n4 = (int)(ELEMS / 4);
    if (i < n4) {
        float4 kv = ((const float4*)K)[i];
        float4 vv = ((const float4*)V)[i];
        __half2* kd = reinterpret_cast<__half2*>(g_Kh) + 2 * i;
        __half2* vd = reinterpret_cast<__half2*>(g_Vh) + 2 * i;
        kd[0] = __floats2half2_rn(kv.x, kv.y);
        kd[1] = __floats2half2_rn(kv.z, kv.w);
        vd[0] = __floats2half2_rn(vv.x, vv.y);
        vd[1] = __floats2half2_rn(vv.z, vv.w);
    }
}

__device__ __forceinline__ float ex2(float x) {
    float y;
    asm volatile("ex2.approx.ftz.f32 %0, %1;" : "=f"(y) : "f"(x));
    return y;
}

__device__ __forceinline__ uint32_t packh2(float a, float b) {
    __half2 h = __floats2half2_rn(a, b);
    return *reinterpret_cast<uint32_t*>(&h);
}

__device__ __forceinline__ void cp_async16(uint32_t dst, const void* src) {
    asm volatile("cp.async.cg.shared.global [%0], [%1], 16;" :: "r"(dst), "l"(src));
}

__device__ __forceinline__ void ldsm_x4(uint32_t& d0, uint32_t& d1, uint32_t& d2, uint32_t& d3,
                                        uint32_t addr) {
    asm volatile("ldmatrix.sync.aligned.m8n8.x4.shared.b16 {%0,%1,%2,%3}, [%4];"
                 : "=r"(d0), "=r"(d1), "=r"(d2), "=r"(d3) : "r"(addr));
}

__device__ __forceinline__ void ldsm_x4_t(uint32_t& d0, uint32_t& d1, uint32_t& d2, uint32_t& d3,
                                          uint32_t addr) {
    asm volatile("ldmatrix.sync.aligned.m8n8.x4.trans.shared.b16 {%0,%1,%2,%3}, [%4];"
                 : "=r"(d0), "=r"(d1), "=r"(d2), "=r"(d3) : "r"(addr));
}

__device__ __forceinline__ void mma16816(float* c,
                                         uint32_t a0, uint32_t a1, uint32_t a2, uint32_t a3,
                                         uint32_t b0, uint32_t b1) {
    asm volatile("mma.sync.aligned.m16n8k16.row.col.f32.f16.f16.f32 "
                 "{%0,%1,%2,%3}, {%4,%5,%6,%7}, {%8,%9}, {%0,%1,%2,%3};"
                 : "+f"(c[0]), "+f"(c[1]), "+f"(c[2]), "+f"(c[3])
                 : "r"(a0), "r"(a1), "r"(a2), "r"(a3), "r"(b0), "r"(b1));
}

__global__ void __launch_bounds__(128)
fa_fwd(const float* __restrict__ Qg, float* __restrict__ Og) {
    // double-buffered fp16 tiles
    __shared__ __align__(16) __half Ksh[2][BN * KST];
    __shared__ __align__(16) __half Vsh[2][BN * KST];

    const int bh    = blockIdx.y;
    const int mbase = blockIdx.x * BM;
    const float*  Qp = Qg   + (size_t)bh * S * D;
    const __half* Kp = g_Kh + (size_t)bh * S * D;
    const __half* Vp = g_Vh + (size_t)bh * S * D;
    float*        Op = Og   + (size_t)bh * S * D;

    const int tid  = threadIdx.x;
    const int warp = tid >> 5;
    const int lane = tid & 31;
    const int g    = lane >> 2;
    const int q    = lane & 3;
    const int r0   = mbase + warp * 16 + g;
    const int r1   = r0 + 8;

    const float cs = 0.125f * 1.4426950408889634f;  // 1/sqrt(D) * log2(e)

    // ---- Q fragments (scaled fp16) ----
    uint32_t qa[4][4];
#pragma unroll
    for (int kt = 0; kt < 4; ++kt) {
        const int c = kt * 16 + 2 * q;
        float2 t;
        t = *(const float2*)(Qp + (size_t)r0 * D + c);
        qa[kt][0] = packh2(t.x * cs, t.y * cs);
        t = *(const float2*)(Qp + (size_t)r1 * D + c);
        qa[kt][1] = packh2(t.x * cs, t.y * cs);
        t = *(const float2*)(Qp + (size_t)r0 * D + c + 8);
        qa[kt][2] = packh2(t.x * cs, t.y * cs);
        t = *(const float2*)(Qp + (size_t)r1 * D + c + 8);
        qa[kt][3] = packh2(t.x * cs, t.y * cs);
    }

    float oacc[8][4];
#pragma unroll
    for (int j = 0; j < 8; ++j)
#pragma unroll
        for (int k = 0; k < 4; ++k) oacc[j][k] = 0.f;

    const float NEGINF = -1e30f;
    float mrow0 = NEGINF, mrow1 = NEGINF;
    float lrow0 = 0.f, lrow1 = 0.f;

    uint32_t ks_base[2], vs_base[2];
    ks_base[0] = (uint32_t)__cvta_generic_to_shared(&Ksh[0][0]);
    ks_base[1] = (uint32_t)__cvta_generic_to_shared(&Ksh[1][0]);
    vs_base[0] = (uint32_t)__cvta_generic_to_shared(&Vsh[0][0]);
    vs_base[1] = (uint32_t)__cvta_generic_to_shared(&Vsh[1][0]);

    // cp.async tile issue: 64 rows x 128B per tensor = 512 chunks of 16B, 4/thread
    auto issue_tile = [&](int nt, int stage) {
        const __half* Kt = Kp + (size_t)nt * BN * D;
        const __half* Vt = Vp + (size_t)nt * BN * D;
#pragma unroll
        for (int i = 0; i < 4; ++i) {
            const int idx = tid + i * 128;
            const int row = idx >> 3;
            const int col = (idx & 7) * 8;  // halves
            const uint32_t off = 2u * (uint32_t)(row * KST + col);
            cp_async16(ks_base[stage] + off, Kt + row * D + col);
            cp_async16(vs_base[stage] + off, Vt + row * D + col);
        }
        asm volatile("cp.async.commit_group;");
    };

    // ldmatrix per-lane address components
    const int lj = lane >> 3, lr = lane & 7;
    const int krow = (lj & 2) * 4 + lr;
    const int kcol = (lj & 1) * 8;
    const int vrow = (lj & 1) * 8 + lr;
    const int vcol = (lj & 2) * 4;

    issue_tile(0, 0);

    for (int nt = 0; nt < NT; ++nt) {
        const int cur = nt & 1;

        asm volatile("cp.async.wait_group 0;");
        __syncthreads();

        if (nt + 1 < NT) issue_tile(nt + 1, cur ^ 1);

        // ---- S = (Q*cs) K^T ----
        float sacc[8][4];
#pragma unroll
        for (int j = 0; j < 8; ++j)
#pragma unroll
            for (int k = 0; k < 4; ++k) sacc[j][k] = 0.f;

#pragma unroll
        for (int np = 0; np < 4; ++np) {
#pragma unroll
            for (int kt = 0; kt < 4; ++kt) {
                uint32_t b0, b1, b2, b3;
                const uint32_t addr =
                    ks_base[cur] + 2u * (uint32_t)((np * 16 + krow) * KST + kt * 16 + kcol);
                ldsm_x4(b0, b1, b2, b3, addr);
                mma16816(sacc[2 * np],     qa[kt][0], qa[kt][1], qa[kt][2], qa[kt][3], b0, b1);
                mma16816(sacc[2 * np + 1], qa[kt][0], qa[kt][1], qa[kt][2], qa[kt][3], b2, b3);
            }
        }

        // ---- online softmax (base-2) ----
        float mx0 = NEGINF, mx1 = NEGINF;
#pragma unroll
        for (int j = 0; j < 8; ++j) {
            mx0 = fmaxf(mx0, fmaxf(sacc[j][0], sacc[j][1]));
            mx1 = fmaxf(mx1, fmaxf(sacc[j][2], sacc[j][3]));
        }
        mx0 = fmaxf(mx0, __shfl_xor_sync(0xffffffffu, mx0, 1));
        mx0 = fmaxf(mx0, __shfl_xor_sync(0xffffffffu, mx0, 2));
        mx1 = fmaxf(mx1, __shfl_xor_sync(0xffffffffu, mx1, 1));
        mx1 = fmaxf(mx1, __shfl_xor_sync(0xffffffffu, mx1, 2));

        const float mn0 = fmaxf(mrow0, mx0);
        const float mn1 = fmaxf(mrow1, mx1);
        const float al0 = ex2(mrow0 - mn0);
        const float al1 = ex2(mrow1 - mn1);
        mrow0 = mn0; mrow1 = mn1;

        float rs0 = 0.f, rs1 = 0.f;
        uint32_t pa[8], pb[8];
#pragma unroll
        for (int j = 0; j < 8; ++j) {
            const float p0 = ex2(sacc[j][0] - mn0);
            const float p1 = ex2(sacc[j][1] - mn0);
            const float p2 = ex2(sacc[j][2] - mn1);
            const float p3 = ex2(sacc[j][3] - mn1);
            rs0 += p0 + p1;
            rs1 += p2 + p3;
            pa[j] = packh2(p0, p1);
            pb[j] = packh2(p2, p3);
        }
        rs0 += __shfl_xor_sync(0xffffffffu, rs0, 1);
        rs0 += __shfl_xor_sync(0xffffffffu, rs0, 2);
        rs1 += __shfl_xor_sync(0xffffffffu, rs1, 1);
        rs1 += __shfl_xor_sync(0xffffffffu, rs1, 2);
        lrow0 = lrow0 * al0 + rs0;
        lrow1 = lrow1 * al1 + rs1;

#pragma unroll
        for (int j = 0; j < 8; ++j) {
            oacc[j][0] *= al0; oacc[j][1] *= al0;
            oacc[j][2] *= al1; oacc[j][3] *= al1;
        }

        // ---- O += P V ----
#pragma unroll
        for (int kt = 0; kt < 4; ++kt) {
            const uint32_t a0 = pa[2 * kt], a1 = pb[2 * kt];
            const uint32_t a2 = pa[2 * kt + 1], a3 = pb[2 * kt + 1];
#pragma unroll
            for (int np = 0; np < 4; ++np) {
                uint32_t b0, b1, b2, b3;
                const uint32_t addr =
                    vs_base[cur] + 2u * (uint32_t)((kt * 16 + vrow) * KST + np * 16 + vcol);
                ldsm_x4_t(b0, b1, b2, b3, addr);
                mma16816(oacc[2 * np],     a0, a1, a2, a3, b0, b1);
                mma16816(oacc[2 * np + 1], a0, a1, a2, a3, b2, b3);
            }
        }

        __syncthreads();
    }

    // ---- epilogue ----
    const float inv0 = 1.f / lrow0;
    const float inv1 = 1.f / lrow1;
#pragma unroll
    for (int j = 0; j < 8; ++j) {
        float2 o0 = make_float2(oacc[j][0] * inv0, oacc[j][1] * inv0);
        float2 o1 = make_float2(oacc[j][2] * inv1, oacc[j][3] * inv1);
        *(float2*)(Op + (size_t)r0 * D + j * 8 + 2 * q) = o0;
        *(float2*)(Op + (size_t)r1 * D + j * 8 + 2 * q) = o1;
    }
}

}  // namespace

extern "C" void kernel_launch(void* const* d_in, const int* /*in_sizes*/, int /*n_in*/,
                              void* d_out, int /*out_size*/) {
    const float* Q = (const float*)d_in[0];
    const float* K = (const float*)d_in[1];
    const float* V = (const float*)d_in[2];
    float* O = (float*)d_out;

    const int n4 = (int)(ELEMS / 4);
    cvt_kv<<<(n4 + 255) / 256, 256>>>(K, V);

    dim3 grid(S / BM, BH);
    fa_fwd<<<grid, 128>>>(Q, O);
}